// round 9
// baseline (speedup 1.0000x reference)
#include <cuda_runtime.h>
#include <cstdint>
#include <cstddef>

// ---------------------------------------------------------------------------
// WaveNet forward.
// Layers: fp32 FFMA2 kernels, scalar-weight smem (20KB), NPAIR-templated
//   tiles (64-step main / 32-step tail) for 5-6 CTAs/SM occupancy.
// Skip + post1 GEMMs: warp mma.sync m16n8k8 tf32 (proven R8), fused bias+ELU.
// Device globals only ever referenced from device code (R8 ATS lesson).
// ---------------------------------------------------------------------------

#define T_LEN   8192
#define NRES    32
#define NSKIP   512
#define NFEAT   8
#define NLAY    50
#define OUTLEN  3077
#define BATCH   8
#define MROWS   (BATCH * OUTLEN)      // 24616
#define KSKIP   (NLAY * NRES)         // 1600

// ------------------------- device scratch (static) -------------------------
__device__ float g_hA[(size_t)BATCH * T_LEN * NRES];
__device__ float g_hB[(size_t)BATCH * T_LEN * NRES];
__device__ float g_G[(size_t)MROWS * KSKIP];                // [row][k], K-major
__device__ float g_skip[(size_t)MROWS * NSKIP];             // elu(skip_sum+bias)
__device__ float g_y2[(size_t)MROWS * NSKIP];               // elu(post1 out)
__device__ float g_WskipT[(size_t)NSKIP * KSKIP];           // [s][k], K-major
__device__ float g_bskip[NSKIP];

// ------------------------------ helpers ------------------------------------
__device__ __forceinline__ uint32_t f2tf(float x) {
    uint32_t r;
    asm("cvt.rna.tf32.f32 %0, %1;" : "=r"(r) : "f"(x));
    return r;
}
__device__ __forceinline__ float2 ffma2(float2 a, float2 b, float2 c) {
    float2 d;
    asm("fma.rn.f32x2 %0, %1, %2, %3;"
        : "=l"(*reinterpret_cast<unsigned long long*>(&d))
        : "l"(*reinterpret_cast<unsigned long long*>(&a)),
          "l"(*reinterpret_cast<unsigned long long*>(&b)),
          "l"(*reinterpret_cast<unsigned long long*>(&c)));
    return d;
}
__device__ __forceinline__ float2 f2(float x, float y) { return make_float2(x, y); }
__device__ __forceinline__ float sigmoid_f(float x) {
    x = fminf(fmaxf(x, -30.f), 30.f);
    return __fdividef(1.f, 1.f + __expf(-x));
}
__device__ __forceinline__ float tanh_f(float x) {
    x = fminf(fmaxf(x, -15.f), 15.f);
    float e = __expf(-2.f * x);
    return __fdividef(1.f - e, 1.f + e);
}
__device__ __forceinline__ float eluf(float x) {
    return x > 0.f ? x : (__expf(x) - 1.f);
}

// ------------------------------ input conv ---------------------------------
__global__ __launch_bounds__(256) void in_conv_kernel(
    const float* __restrict__ x, const float* __restrict__ w_in,
    const float* __restrict__ b_in)
{
    int b = blockIdx.y;
    int t = blockIdx.x * 8 + (threadIdx.x >> 5);
    int o = threadIdx.x & 31;
    float w[NFEAT];
#pragma unroll
    for (int f = 0; f < NFEAT; ++f) w[f] = w_in[o * NFEAT + f];
    const float* xp = x + ((size_t)b * T_LEN + t) * NFEAT;
    float acc = b_in[o];
#pragma unroll
    for (int f = 0; f < NFEAT; ++f) acc = fmaf(w[f], xp[f], acc);
    g_hA[((size_t)b * T_LEN + t) * NRES + o] = acc;
}

// ------------------------------ repacks ------------------------------------
__global__ __launch_bounds__(256) void repack_wskipT_kernel(const float* __restrict__ w_skip)
{
    int idx = blockIdx.x * 256 + threadIdx.x;       // < 512*1600
    int s = idx / KSKIP, k = idx - s * KSKIP;
    g_WskipT[idx] = w_skip[(size_t)(k >> 5) * (NSKIP * NRES) + (size_t)s * NRES + (k & 31)];
}
__global__ __launch_bounds__(256) void bias_sum_kernel(const float* __restrict__ b_skip)
{
    int s = blockIdx.x * 256 + threadIdx.x;
    if (s < NSKIP) {
        float a = 0.f;
#pragma unroll
        for (int i = 0; i < NLAY; ++i) a += b_skip[i * NSKIP + s];
        g_bskip[s] = a;
    }
}

// ------------------------------ layer kernel -------------------------------
// Templated on NPAIR (time-pairs per warp).  Block covers 16*NPAIR steps.
// smem: 5 scalar weight arrays [c][o] (20KB) + hs0/hs1 [c][8*NPAIR+2 pairs]
//       + 3 bias arrays.  NPAIR=4: 38272B, 5 CTAs/SM.  NPAIR=2: 30080B, 6.
template <int NPAIR>
__global__ __launch_bounds__(256, (NPAIR == 4) ? 5 : 6)
void layer_kernel(
    const float* __restrict__ w_sig, const float* __restrict__ b_sig,
    const float* __restrict__ w_tanh, const float* __restrict__ b_tanh,
    const float* __restrict__ w_res, const float* __restrict__ b_res,
    int layer, int d, int Lout, int goff, int ping)
{
    constexpr int HSS = 8 * NPAIR + 2;     // hs stride in float2 (even -> f4 ok)
    constexpr int LTS = 16 * NPAIR;        // timesteps per block

    extern __shared__ float smf[];
    float*  ws0 = smf;                      // [c*32+o]
    float*  ws1 = smf + 1024;
    float*  wt0 = smf + 2048;
    float*  wt1 = smf + 3072;
    float*  wrs = smf + 4096;
    float2* hs0 = reinterpret_cast<float2*>(smf + 5120);    // [c*HSS + pair]
    float2* hs1 = hs0 + 32 * HSS;
    float*  bs  = reinterpret_cast<float*>(hs1 + 32 * HSS);
    float*  bt  = bs + 32;
    float*  br  = bs + 64;

    const float* h_in = ping ? g_hB : g_hA;
    float* h_out      = ping ? g_hA : g_hB;

    int tid = threadIdx.x;
    int b = blockIdx.y;
    int t0 = blockIdx.x * LTS;

    // weights -> shared (scalar, [c][o]; lane=o -> conflict-free STS)
    const float* wsp = w_sig  + (size_t)layer * 2048;   // [o][c][tap]
    const float* wtp = w_tanh + (size_t)layer * 2048;
    const float* wrp = w_res  + (size_t)layer * 1024;   // [o][c]
#pragma unroll
    for (int p = tid; p < 1024; p += 256) {
        int o = p & 31, c = p >> 5;
        ws0[c * 32 + o] = wsp[(o * 32 + c) * 2];
        ws1[c * 32 + o] = wsp[(o * 32 + c) * 2 + 1];
        wt0[c * 32 + o] = wtp[(o * 32 + c) * 2];
        wt1[c * 32 + o] = wtp[(o * 32 + c) * 2 + 1];
        wrs[c * 32 + o] = wrp[o * 32 + c];
    }
    if (tid < 32) {
        bs[tid] = b_sig[layer * 32 + tid];
        bt[tid] = b_tanh[layer * 32 + tid];
        br[tid] = b_res[layer * 32 + tid];
    }

    // h tiles -> shared, transposed to [c][t]
    const float* hb = h_in + (size_t)b * T_LEN * NRES;
    float* hs0f = reinterpret_cast<float*>(hs0);
    float* hs1f = reinterpret_cast<float*>(hs1);
#pragma unroll
    for (int idx = tid; idx < LTS * 32; idx += 256) {
        int j = idx >> 5, c = idx & 31;
        int t = t0 + j;
        float v0 = 0.f, v1 = 0.f;
        if (t < Lout) {
            v0 = hb[(size_t)t * NRES + c];
            v1 = hb[(size_t)(t + d) * NRES + c];
        }
        hs0f[c * (2 * HSS) + j] = v0;
        hs1f[c * (2 * HSS) + j] = v1;
    }
    __syncthreads();

    int w = tid >> 5, o = tid & 31;
    int jp0 = w * NPAIR;

    float2 ps[NPAIR], pt[NPAIR];
#pragma unroll
    for (int p = 0; p < NPAIR; ++p) {
        ps[p] = f2(bs[o], bs[o]);
        pt[p] = f2(bt[o], bt[o]);
    }

#pragma unroll 4
    for (int c = 0; c < 32; ++c) {
        float a0 = ws0[c * 32 + o], a1 = ws1[c * 32 + o];
        float u0 = wt0[c * 32 + o], u1 = wt1[c * 32 + o];
        float2 W0 = f2(a0, a0), W1 = f2(a1, a1);
        float2 V0 = f2(u0, u0), V1 = f2(u1, u1);
        const float4* ap = reinterpret_cast<const float4*>(&hs0[c * HSS + jp0]);
        const float4* ep = reinterpret_cast<const float4*>(&hs1[c * HSS + jp0]);
#pragma unroll
        for (int q = 0; q < NPAIR / 2; ++q) {
            float4 A = ap[q], E = ep[q];
            ps[2*q]   = ffma2(W0, f2(A.x, A.y), ps[2*q]);
            ps[2*q]   = ffma2(W1, f2(E.x, E.y), ps[2*q]);
            ps[2*q+1] = ffma2(W0, f2(A.z, A.w), ps[2*q+1]);
            ps[2*q+1] = ffma2(W1, f2(E.z, E.w), ps[2*q+1]);
            pt[2*q]   = ffma2(V0, f2(A.x, A.y), pt[2*q]);
            pt[2*q]   = ffma2(V1, f2(E.x, E.y), pt[2*q]);
            pt[2*q+1] = ffma2(V0, f2(A.z, A.w), pt[2*q+1]);
            pt[2*q+1] = ffma2(V1, f2(E.z, E.w), pt[2*q+1]);
        }
    }

    // gated activation
    float2 g[NPAIR];
#pragma unroll
    for (int p = 0; p < NPAIR; ++p) {
        g[p].x = sigmoid_f(ps[p].x) * tanh_f(pt[p].x);
        g[p].y = sigmoid_f(ps[p].y) * tanh_f(pt[p].y);
    }

    // residual init: br + h[t+d] (own channel)
    float2 r[NPAIR];
#pragma unroll
    for (int p = 0; p < NPAIR; ++p) {
        float2 h1o = hs1[o * HSS + jp0 + p];
        r[p] = f2(br[o] + h1o.x, br[o] + h1o.y);
    }

    // stash g into hs0's warp-private columns (disjoint per warp)
#pragma unroll
    for (int p = 0; p < NPAIR; ++p) hs0[o * HSS + jp0 + p] = g[p];
    __syncwarp();

    // res matvec: r += Wr * g (broadcast reads of warp-private g columns)
#pragma unroll 4
    for (int c = 0; c < 32; ++c) {
        float rv = wrs[c * 32 + o];
        float2 wv = f2(rv, rv);
        const float4* gp = reinterpret_cast<const float4*>(&hs0[c * HSS + jp0]);
#pragma unroll
        for (int q = 0; q < NPAIR / 2; ++q) {
            float4 G = gp[q];
            r[2*q]   = ffma2(wv, f2(G.x, G.y), r[2*q]);
            r[2*q+1] = ffma2(wv, f2(G.z, G.w), r[2*q+1]);
        }
    }

    // stores
    float* Gb  = g_G + (size_t)b * OUTLEN * KSKIP + (size_t)layer * NRES;
    float* hob = h_out + (size_t)b * T_LEN * NRES;
#pragma unroll
    for (int p = 0; p < NPAIR; ++p) {
        int t = t0 + w * (2 * NPAIR) + 2 * p;
        if (t < Lout) {
            hob[(size_t)t * NRES + o] = r[p].x;
            int u = t - goff;
            if (u >= 0) Gb[(size_t)u * KSKIP + o] = g[p].x;
        }
        if (t + 1 < Lout) {
            hob[(size_t)(t + 1) * NRES + o] = r[p].y;
            int u = t + 1 - goff;
            if (u >= 0) Gb[(size_t)u * KSKIP + o] = g[p].y;
        }
    }
}

#define LK4_SMEM 38272
#define LK2_SMEM 30080

// ------------------------- mma.sync tf32 GEMM core (frozen, R8) ------------
#define GPAD 36
#define GTILE (128 * GPAD)                 // 4608 floats per tile
#define GSM_BYTES (2 * 2 * GTILE * 4)      // 73728 bytes

template <int KDIM>
__device__ __forceinline__ void mma_gemm_core(
    const float* __restrict__ A, const float* __restrict__ B,
    const float* __restrict__ bias, float* __restrict__ C, int M)
{
    extern __shared__ float sm[];
    int tid = threadIdx.x;
    int wid = tid >> 5, lane = tid & 31;
    int g = lane >> 2, tg = lane & 3;
    int nBase = blockIdx.x * 128;      // n fastest -> 4 n-blocks share A in L2
    int mBase = blockIdx.y * 128;
    int mwarp = wid >> 2, nwarp = wid & 3;

    float acc[4][4][4] = {};

    float4 aR[4], bR[4];
    auto fetch = [&](int kt) {
#pragma unroll
        for (int i = 0; i < 4; ++i) {
            int gg = tid + i * 256;
            int row = gg >> 3, c4 = gg & 7;
            int gr = mBase + row;
            aR[i] = (gr < M)
                ? *reinterpret_cast<const float4*>(A + (size_t)gr * KDIM + kt + c4 * 4)
                : make_float4(0.f, 0.f, 0.f, 0.f);
            bR[i] = *reinterpret_cast<const float4*>(
                B + (size_t)(nBase + row) * KDIM + kt + c4 * 4);
        }
    };
    auto stage = [&](int buf) {
        float* Ab = sm + buf * (2 * GTILE);
        float* Bb = Ab + GTILE;
#pragma unroll
        for (int i = 0; i < 4; ++i) {
            int gg = tid + i * 256;
            int row = gg >> 3, c4 = gg & 7;
            int base = row * GPAD + c4 * 4;
            Ab[base + 0] = __uint_as_float(f2tf(aR[i].x));
            Ab[base + 1] = __uint_as_float(f2tf(aR[i].y));
            Ab[base + 2] = __uint_as_float(f2tf(aR[i].z));
            Ab[base + 3] = __uint_as_float(f2tf(aR[i].w));
            Bb[base + 0] = __uint_as_float(f2tf(bR[i].x));
            Bb[base + 1] = __uint_as_float(f2tf(bR[i].y));
            Bb[base + 2] = __uint_as_float(f2tf(bR[i].z));
            Bb[base + 3] = __uint_as_float(f2tf(bR[i].w));
        }
    };
    auto compute = [&](int buf) {
        const float* Ab = sm + buf * (2 * GTILE);
        const float* Bb = Ab + GTILE;
#pragma unroll
        for (int ks = 0; ks < 4; ++ks) {
            int k0 = ks * 8;
            uint32_t af[4][4];
#pragma unroll
            for (int mt = 0; mt < 4; ++mt) {
                int r = mwarp * 64 + mt * 16 + g;
                af[mt][0] = __float_as_uint(Ab[r * GPAD + k0 + tg]);
                af[mt][1] = __float_as_uint(Ab[(r + 8) * GPAD + k0 + tg]);
                af[mt][2] = __float_as_uint(Ab[r * GPAD + k0 + tg + 4]);
                af[mt][3] = __float_as_uint(Ab[(r + 8) * GPAD + k0 + tg + 4]);
            }
            uint32_t bf[4][2];
#pragma unroll
            for (int nt2 = 0; nt2 < 4; ++nt2) {
                int n = nwarp * 32 + nt2 * 8 + g;
                bf[nt2][0] = __float_as_uint(Bb[n * GPAD + k0 + tg]);
                bf[nt2][1] = __float_as_uint(Bb[n * GPAD + k0 + tg + 4]);
            }
#pragma unroll
            for (int mt = 0; mt < 4; ++mt)
#pragma unroll
                for (int nt2 = 0; nt2 < 4; ++nt2)
                    asm volatile(
                        "mma.sync.aligned.m16n8k8.row.col.f32.tf32.tf32.f32 "
                        "{%0,%1,%2,%3}, {%4,%5,%6,%7}, {%8,%9}, {%0,%1,%2,%3};"
                        : "+f"(acc[mt][nt2][0]), "+f"(acc[mt][nt2][1]),
                          "+f"(acc[mt][nt2][2]), "+f"(acc[mt][nt2][3])
                        : "r"(af[mt][0]), "r"(af[mt][1]), "r"(af[mt][2]), "r"(af[mt][3]),
                          "r"(bf[nt2][0]), "r"(bf[nt2][1]));
        }
    };

    const int nt = KDIM / 32;
    fetch(0);
    stage(0);
    __syncthreads();
    for (int t = 0; t < nt; ++t) {
        int cur = t & 1;
        if (t + 1 < nt) fetch((t + 1) * 32);
        compute(cur);
        if (t + 1 < nt) stage(1 - cur);
        __syncthreads();
    }

    // epilogue: bias + elu
    int cbase = nBase + nwarp * 32;
#pragma unroll
    for (int nt2 = 0; nt2 < 4; ++nt2) {
        int col = cbase + nt2 * 8 + tg * 2;
        float b0 = bias[col], b1 = bias[col + 1];
#pragma unroll
        for (int mt = 0; mt < 4; ++mt) {
            int r0 = mBase + mwarp * 64 + mt * 16 + g;
            int r1 = r0 + 8;
            if (r0 < M) {
                float2 v;
                v.x = eluf(acc[mt][nt2][0] + b0);
                v.y = eluf(acc[mt][nt2][1] + b1);
                *reinterpret_cast<float2*>(C + (size_t)r0 * NSKIP + col) = v;
            }
            if (r1 < M) {
                float2 v;
                v.x = eluf(acc[mt][nt2][2] + b0);
                v.y = eluf(acc[mt][nt2][3] + b1);
                *reinterpret_cast<float2*>(C + (size_t)r1 * NSKIP + col) = v;
            }
        }
    }
}

// Wrapper kernels: device-global pointers formed in DEVICE code.
__global__ __launch_bounds__(256) void skip_gemm_kernel(int M)
{
    mma_gemm_core<KSKIP>(g_G, g_WskipT, g_bskip, g_skip, M);
}
__global__ __launch_bounds__(256) void post1_gemm_kernel(
    const float* __restrict__ w_post1, const float* __restrict__ b_post1, int M)
{
    mma_gemm_core<NSKIP>(g_skip, w_post1, b_post1, g_y2, M);
}

// ------------------------------ post2 --------------------------------------
__global__ __launch_bounds__(256) void post2_kernel(
    const float* __restrict__ w2, const float* __restrict__ b2,
    float* __restrict__ out, int M)
{
    int gw = (blockIdx.x * 256 + threadIdx.x) >> 5;
    int lane = threadIdx.x & 31;
    if (gw >= M) return;
    const float* row = g_y2 + (size_t)gw * NSKIP;
    float acc = 0.f;
#pragma unroll
    for (int k = 0; k < 16; ++k)
        acc = fmaf(row[lane + 32 * k], w2[lane + 32 * k], acc);
#pragma unroll
    for (int s = 16; s > 0; s >>= 1)
        acc += __shfl_xor_sync(0xffffffffu, acc, s);
    if (lane == 0) out[gw] = acc + b2[0];
}

// ------------------------------ launch -------------------------------------
extern "C" void kernel_launch(void* const* d_in, const int* in_sizes, int n_in,
                              void* d_out, int out_size)
{
    const float* x       = (const float*)d_in[0];
    const float* w_in    = (const float*)d_in[1];
    const float* b_in    = (const float*)d_in[2];
    const float* w_sig   = (const float*)d_in[3];
    const float* b_sig   = (const float*)d_in[4];
    const float* w_tanh  = (const float*)d_in[5];
    const float* b_tanh  = (const float*)d_in[6];
    const float* w_skip  = (const float*)d_in[7];
    const float* b_skip  = (const float*)d_in[8];
    const float* w_res   = (const float*)d_in[9];
    const float* b_res   = (const float*)d_in[10];
    const float* w_post1 = (const float*)d_in[11];
    const float* b_post1 = (const float*)d_in[12];
    const float* w_post2 = (const float*)d_in[13];
    const float* b_post2 = (const float*)d_in[14];
    float* out = (float*)d_out;

    cudaFuncSetAttribute(layer_kernel<4>,
                         cudaFuncAttributeMaxDynamicSharedMemorySize, LK4_SMEM);
    cudaFuncSetAttribute(layer_kernel<2>,
                         cudaFuncAttributeMaxDynamicSharedMemorySize, LK2_SMEM);
    cudaFuncSetAttribute(skip_gemm_kernel,
                         cudaFuncAttributeMaxDynamicSharedMemorySize, GSM_BYTES);
    cudaFuncSetAttribute(post1_gemm_kernel,
                         cudaFuncAttributeMaxDynamicSharedMemorySize, GSM_BYTES);

    in_conv_kernel<<<dim3(T_LEN / 8, BATCH), 256>>>(x, w_in, b_in);

    repack_wskipT_kernel<<<(NSKIP * KSKIP) / 256, 256>>>(w_skip);
    bias_sum_kernel<<<2, 256>>>(b_skip);

    static const int dil10[10] = {1, 2, 4, 8, 16, 32, 64, 128, 256, 512};
    int L = T_LEN;
    for (int i = 0; i < NLAY; ++i) {
        int d = dil10[i % 10];
        int Lout = L - d;
        int goff = Lout - OUTLEN;
        if (Lout >= 5125) {
            int nb = (Lout + 63) / 64;
            layer_kernel<4><<<dim3(nb, BATCH), 256, LK4_SMEM>>>(
                w_sig, b_sig, w_tanh, b_tanh, w_res, b_res, i, d, Lout, goff, i & 1);
        } else {
            int nb = (Lout + 31) / 32;
            layer_kernel<2><<<dim3(nb, BATCH), 256, LK2_SMEM>>>(
                w_sig, b_sig, w_tanh, b_tanh, w_res, b_res, i, d, Lout, goff, i & 1);
        }
        L = Lout;
    }

    int M = MROWS;
    dim3 ggrid(NSKIP / 128, (M + 127) / 128);   // n fastest for A reuse in L2
    skip_gemm_kernel<<<ggrid, 256, GSM_BYTES>>>(M);
    post1_gemm_kernel<<<ggrid, 256, GSM_BYTES>>>(w_post1, b_post1, M);
    post2_kernel<<<(M + 7) / 8, 256>>>(w_post2, b_post2, out, M);
}

// round 10
// speedup vs baseline: 1.7467x; 1.7467x over previous
#include <cuda_runtime.h>
#include <cstdint>
#include <cstddef>

// ---------------------------------------------------------------------------
// WaveNet forward.
// Layers: fp32 FFMA2, 96-step tiles, scalar weights pre-packed per layer in
//   g_Wpack (coalesced float4 block load), 4 CTAs/SM.
// Skip + post1 GEMMs: warp mma.sync m16n8k8 tf32 (frozen R8), fused bias+ELU.
// Device globals only referenced from device code (R8 ATS lesson).
// ---------------------------------------------------------------------------

#define T_LEN   8192
#define NRES    32
#define NSKIP   512
#define NFEAT   8
#define NLAY    50
#define OUTLEN  3077
#define BATCH   8
#define MROWS   (BATCH * OUTLEN)      // 24616
#define KSKIP   (NLAY * NRES)         // 1600

#define WPK     5216                  // floats per layer in g_Wpack
#define NPAIR   6
#define HSS     50                    // hs stride in float2
#define LTS     96                    // timesteps per block
#define LK_SMEM 46464                 // (5216 + 2*1600*2) * 4 bytes

// ------------------------- device scratch (static) -------------------------
__device__ float g_hA[(size_t)BATCH * T_LEN * NRES];
__device__ float g_hB[(size_t)BATCH * T_LEN * NRES];
__device__ float g_G[(size_t)MROWS * KSKIP];                // [row][k], K-major
__device__ float g_skip[(size_t)MROWS * NSKIP];             // elu(skip_sum+bias)
__device__ float g_y2[(size_t)MROWS * NSKIP];               // elu(post1 out)
__device__ float g_WskipT[(size_t)NSKIP * KSKIP];           // [s][k], K-major
__device__ float g_bskip[NSKIP];
__device__ float g_Wpack[(size_t)NLAY * WPK];               // packed layer weights

// ------------------------------ helpers ------------------------------------
__device__ __forceinline__ uint32_t f2tf(float x) {
    uint32_t r;
    asm("cvt.rna.tf32.f32 %0, %1;" : "=r"(r) : "f"(x));
    return r;
}
__device__ __forceinline__ float2 ffma2(float2 a, float2 b, float2 c) {
    float2 d;
    asm("fma.rn.f32x2 %0, %1, %2, %3;"
        : "=l"(*reinterpret_cast<unsigned long long*>(&d))
        : "l"(*reinterpret_cast<unsigned long long*>(&a)),
          "l"(*reinterpret_cast<unsigned long long*>(&b)),
          "l"(*reinterpret_cast<unsigned long long*>(&c)));
    return d;
}
__device__ __forceinline__ float2 f2(float x, float y) { return make_float2(x, y); }
__device__ __forceinline__ float sigmoid_f(float x) {
    x = fminf(fmaxf(x, -30.f), 30.f);
    return __fdividef(1.f, 1.f + __expf(-x));
}
__device__ __forceinline__ float tanh_f(float x) {
    x = fminf(fmaxf(x, -15.f), 15.f);
    float e = __expf(-2.f * x);
    return __fdividef(1.f - e, 1.f + e);
}
__device__ __forceinline__ float eluf(float x) {
    return x > 0.f ? x : (__expf(x) - 1.f);
}

// ------------------------------ input conv ---------------------------------
__global__ __launch_bounds__(256) void in_conv_kernel(
    const float* __restrict__ x, const float* __restrict__ w_in,
    const float* __restrict__ b_in)
{
    int b = blockIdx.y;
    int t = blockIdx.x * 8 + (threadIdx.x >> 5);
    int o = threadIdx.x & 31;
    float w[NFEAT];
#pragma unroll
    for (int f = 0; f < NFEAT; ++f) w[f] = w_in[o * NFEAT + f];
    const float* xp = x + ((size_t)b * T_LEN + t) * NFEAT;
    float acc = b_in[o];
#pragma unroll
    for (int f = 0; f < NFEAT; ++f) acc = fmaf(w[f], xp[f], acc);
    g_hA[((size_t)b * T_LEN + t) * NRES + o] = acc;
}

// ------------------------------ repacks ------------------------------------
__global__ __launch_bounds__(256) void repack_wskipT_kernel(const float* __restrict__ w_skip)
{
    int idx = blockIdx.x * 256 + threadIdx.x;       // < 512*1600
    int s = idx / KSKIP, k = idx - s * KSKIP;
    g_WskipT[idx] = w_skip[(size_t)(k >> 5) * (NSKIP * NRES) + (size_t)s * NRES + (k & 31)];
}
__global__ __launch_bounds__(256) void bias_sum_kernel(const float* __restrict__ b_skip)
{
    int s = blockIdx.x * 256 + threadIdx.x;
    if (s < NSKIP) {
        float a = 0.f;
#pragma unroll
        for (int i = 0; i < NLAY; ++i) a += b_skip[i * NSKIP + s];
        g_bskip[s] = a;
    }
}

// One-time weight pack: g_Wpack[layer][i] in smem destination order:
//   [0,1024)  ws0[c*32+o]   [1024,2048) ws1   [2048,3072) wt0
//   [3072,4096) wt1         [4096,5120) wrs
//   [5120,5152) bs  [5152,5184) bt  [5184,5216) br
__global__ __launch_bounds__(256) void repack_weights_kernel(
    const float* __restrict__ w_sig, const float* __restrict__ b_sig,
    const float* __restrict__ w_tanh, const float* __restrict__ b_tanh,
    const float* __restrict__ w_res, const float* __restrict__ b_res)
{
    int idx = blockIdx.x * 256 + threadIdx.x;
    if (idx >= NLAY * WPK) return;
    int layer = idx / WPK;
    int i = idx - layer * WPK;
    float v;
    if (i < 4096) {
        int arr = i >> 10;                 // 0:ws0 1:ws1 2:wt0 3:wt1
        int j = i & 1023;
        int o = j & 31, c = j >> 5;
        const float* src = (arr < 2) ? w_sig : w_tanh;
        int tap = arr & 1;
        v = src[(size_t)layer * 2048 + (o * 32 + c) * 2 + tap];
    } else if (i < 5120) {
        int j = i - 4096;
        int o = j & 31, c = j >> 5;
        v = w_res[(size_t)layer * 1024 + o * 32 + c];
    } else if (i < 5152) {
        v = b_sig[layer * 32 + (i - 5120)];
    } else if (i < 5184) {
        v = b_tanh[layer * 32 + (i - 5152)];
    } else {
        v = b_res[layer * 32 + (i - 5184)];
    }
    g_Wpack[idx] = v;
}

// ------------------------------ layer kernel -------------------------------
__global__ __launch_bounds__(256, 4)
void layer_kernel(int layer, int d, int Lout, int goff, int ping)
{
    extern __shared__ float smf[];
    float*  ws0 = smf;                      // [c*32+o]
    float*  ws1 = smf + 1024;
    float*  wt0 = smf + 2048;
    float*  wt1 = smf + 3072;
    float*  wrs = smf + 4096;
    float*  bs  = smf + 5120;
    float*  bt  = smf + 5152;
    float*  br  = smf + 5184;
    float2* hs0 = reinterpret_cast<float2*>(smf + WPK);     // [c*HSS + pair]
    float2* hs1 = hs0 + 32 * HSS;

    const float* h_in = ping ? g_hB : g_hA;
    float* h_out      = ping ? g_hA : g_hB;

    int tid = threadIdx.x;
    int b = blockIdx.y;
    int t0 = blockIdx.x * LTS;

    // coalesced float4 copy of packed weights+biases (WPK/4 = 1304 float4)
    {
        const float4* wp = reinterpret_cast<const float4*>(g_Wpack + (size_t)layer * WPK);
        float4* sp = reinterpret_cast<float4*>(smf);
#pragma unroll
        for (int p = tid; p < WPK / 4; p += 256) sp[p] = wp[p];
    }

    // h tiles -> shared, transposed to [c][t]
    const float* hb = h_in + (size_t)b * T_LEN * NRES;
    float* hs0f = reinterpret_cast<float*>(hs0);
    float* hs1f = reinterpret_cast<float*>(hs1);
#pragma unroll
    for (int idx = tid; idx < LTS * 32; idx += 256) {
        int j = idx >> 5, c = idx & 31;
        int t = t0 + j;
        float v0 = 0.f, v1 = 0.f;
        if (t < Lout) {
            v0 = hb[(size_t)t * NRES + c];
            v1 = hb[(size_t)(t + d) * NRES + c];
        }
        hs0f[c * (2 * HSS) + j] = v0;
        hs1f[c * (2 * HSS) + j] = v1;
    }
    __syncthreads();

    int w = tid >> 5, o = tid & 31;
    int jp0 = w * NPAIR;

    float2 ps[NPAIR], pt[NPAIR];
#pragma unroll
    for (int p = 0; p < NPAIR; ++p) {
        ps[p] = f2(bs[o], bs[o]);
        pt[p] = f2(bt[o], bt[o]);
    }

#pragma unroll 4
    for (int c = 0; c < 32; ++c) {
        float a0 = ws0[c * 32 + o], a1 = ws1[c * 32 + o];
        float u0 = wt0[c * 32 + o], u1 = wt1[c * 32 + o];
        float2 W0 = f2(a0, a0), W1 = f2(a1, a1);
        float2 V0 = f2(u0, u0), V1 = f2(u1, u1);
        const float4* ap = reinterpret_cast<const float4*>(&hs0[c * HSS + jp0]);
        const float4* ep = reinterpret_cast<const float4*>(&hs1[c * HSS + jp0]);
#pragma unroll
        for (int q = 0; q < NPAIR / 2; ++q) {
            float4 A = ap[q], E = ep[q];
            ps[2*q]   = ffma2(W0, f2(A.x, A.y), ps[2*q]);
            ps[2*q]   = ffma2(W1, f2(E.x, E.y), ps[2*q]);
            ps[2*q+1] = ffma2(W0, f2(A.z, A.w), ps[2*q+1]);
            ps[2*q+1] = ffma2(W1, f2(E.z, E.w), ps[2*q+1]);
            pt[2*q]   = ffma2(V0, f2(A.x, A.y), pt[2*q]);
            pt[2*q]   = ffma2(V1, f2(E.x, E.y), pt[2*q]);
            pt[2*q+1] = ffma2(V0, f2(A.z, A.w), pt[2*q+1]);
            pt[2*q+1] = ffma2(V1, f2(E.z, E.w), pt[2*q+1]);
        }
    }

    // gated activation
    float2 g[NPAIR];
#pragma unroll
    for (int p = 0; p < NPAIR; ++p) {
        g[p].x = sigmoid_f(ps[p].x) * tanh_f(pt[p].x);
        g[p].y = sigmoid_f(ps[p].y) * tanh_f(pt[p].y);
    }

    // residual init: br + h[t+d] (own channel)
    float2 r[NPAIR];
#pragma unroll
    for (int p = 0; p < NPAIR; ++p) {
        float2 h1o = hs1[o * HSS + jp0 + p];
        r[p] = f2(br[o] + h1o.x, br[o] + h1o.y);
    }

    // stash g into hs0's warp-private columns (disjoint per warp)
#pragma unroll
    for (int p = 0; p < NPAIR; ++p) hs0[o * HSS + jp0 + p] = g[p];
    __syncwarp();

    // res matvec: r += Wr * g (broadcast reads of warp-private g columns)
#pragma unroll 4
    for (int c = 0; c < 32; ++c) {
        float rv = wrs[c * 32 + o];
        float2 wv = f2(rv, rv);
        const float4* gp = reinterpret_cast<const float4*>(&hs0[c * HSS + jp0]);
#pragma unroll
        for (int q = 0; q < NPAIR / 2; ++q) {
            float4 G = gp[q];
            r[2*q]   = ffma2(wv, f2(G.x, G.y), r[2*q]);
            r[2*q+1] = ffma2(wv, f2(G.z, G.w), r[2*q+1]);
        }
    }

    // stores
    float* Gb  = g_G + (size_t)b * OUTLEN * KSKIP + (size_t)layer * NRES;
    float* hob = h_out + (size_t)b * T_LEN * NRES;
#pragma unroll
    for (int p = 0; p < NPAIR; ++p) {
        int t = t0 + w * (2 * NPAIR) + 2 * p;
        if (t < Lout) {
            hob[(size_t)t * NRES + o] = r[p].x;
            int u = t - goff;
            if (u >= 0) Gb[(size_t)u * KSKIP + o] = g[p].x;
        }
        if (t + 1 < Lout) {
            hob[(size_t)(t + 1) * NRES + o] = r[p].y;
            int u = t + 1 - goff;
            if (u >= 0) Gb[(size_t)u * KSKIP + o] = g[p].y;
        }
    }
}

// ------------------------- mma.sync tf32 GEMM core (frozen, R8) ------------
#define GPAD 36
#define GTILE (128 * GPAD)                 // 4608 floats per tile
#define GSM_BYTES (2 * 2 * GTILE * 4)      // 73728 bytes

template <int KDIM>
__device__ __forceinline__ void mma_gemm_core(
    const float* __restrict__ A, const float* __restrict__ B,
    const float* __restrict__ bias, float* __restrict__ C, int M)
{
    extern __shared__ float sm[];
    int tid = threadIdx.x;
    int wid = tid >> 5, lane = tid & 31;
    int g = lane >> 2, tg = lane & 3;
    int nBase = blockIdx.x * 128;      // n fastest -> 4 n-blocks share A in L2
    int mBase = blockIdx.y * 128;
    int mwarp = wid >> 2, nwarp = wid & 3;

    float acc[4][4][4] = {};

    float4 aR[4], bR[4];
    auto fetch = [&](int kt) {
#pragma unroll
        for (int i = 0; i < 4; ++i) {
            int gg = tid + i * 256;
            int row = gg >> 3, c4 = gg & 7;
            int gr = mBase + row;
            aR[i] = (gr < M)
                ? *reinterpret_cast<const float4*>(A + (size_t)gr * KDIM + kt + c4 * 4)
                : make_float4(0.f, 0.f, 0.f, 0.f);
            bR[i] = *reinterpret_cast<const float4*>(
                B + (size_t)(nBase + row) * KDIM + kt + c4 * 4);
        }
    };
    auto stage = [&](int buf) {
        float* Ab = sm + buf * (2 * GTILE);
        float* Bb = Ab + GTILE;
#pragma unroll
        for (int i = 0; i < 4; ++i) {
            int gg = tid + i * 256;
            int row = gg >> 3, c4 = gg & 7;
            int base = row * GPAD + c4 * 4;
            Ab[base + 0] = __uint_as_float(f2tf(aR[i].x));
            Ab[base + 1] = __uint_as_float(f2tf(aR[i].y));
            Ab[base + 2] = __uint_as_float(f2tf(aR[i].z));
            Ab[base + 3] = __uint_as_float(f2tf(aR[i].w));
            Bb[base + 0] = __uint_as_float(f2tf(bR[i].x));
            Bb[base + 1] = __uint_as_float(f2tf(bR[i].y));
            Bb[base + 2] = __uint_as_float(f2tf(bR[i].z));
            Bb[base + 3] = __uint_as_float(f2tf(bR[i].w));
        }
    };
    auto compute = [&](int buf) {
        const float* Ab = sm + buf * (2 * GTILE);
        const float* Bb = Ab + GTILE;
#pragma unroll
        for (int ks = 0; ks < 4; ++ks) {
            int k0 = ks * 8;
            uint32_t af[4][4];
#pragma unroll
            for (int mt = 0; mt < 4; ++mt) {
                int r = mwarp * 64 + mt * 16 + g;
                af[mt][0] = __float_as_uint(Ab[r * GPAD + k0 + tg]);
                af[mt][1] = __float_as_uint(Ab[(r + 8) * GPAD + k0 + tg]);
                af[mt][2] = __float_as_uint(Ab[r * GPAD + k0 + tg + 4]);
                af[mt][3] = __float_as_uint(Ab[(r + 8) * GPAD + k0 + tg + 4]);
            }
            uint32_t bf[4][2];
#pragma unroll
            for (int nt2 = 0; nt2 < 4; ++nt2) {
                int n = nwarp * 32 + nt2 * 8 + g;
                bf[nt2][0] = __float_as_uint(Bb[n * GPAD + k0 + tg]);
                bf[nt2][1] = __float_as_uint(Bb[n * GPAD + k0 + tg + 4]);
            }
#pragma unroll
            for (int mt = 0; mt < 4; ++mt)
#pragma unroll
                for (int nt2 = 0; nt2 < 4; ++nt2)
                    asm volatile(
                        "mma.sync.aligned.m16n8k8.row.col.f32.tf32.tf32.f32 "
                        "{%0,%1,%2,%3}, {%4,%5,%6,%7}, {%8,%9}, {%0,%1,%2,%3};"
                        : "+f"(acc[mt][nt2][0]), "+f"(acc[mt][nt2][1]),
                          "+f"(acc[mt][nt2][2]), "+f"(acc[mt][nt2][3])
                        : "r"(af[mt][0]), "r"(af[mt][1]), "r"(af[mt][2]), "r"(af[mt][3]),
                          "r"(bf[nt2][0]), "r"(bf[nt2][1]));
        }
    };

    const int nt = KDIM / 32;
    fetch(0);
    stage(0);
    __syncthreads();
    for (int t = 0; t < nt; ++t) {
        int cur = t & 1;
        if (t + 1 < nt) fetch((t + 1) * 32);
        compute(cur);
        if (t + 1 < nt) stage(1 - cur);
        __syncthreads();
    }

    // epilogue: bias + elu
    int cbase = nBase + nwarp * 32;
#pragma unroll
    for (int nt2 = 0; nt2 < 4; ++nt2) {
        int col = cbase + nt2 * 8 + tg * 2;
        float b0 = bias[col], b1 = bias[col + 1];
#pragma unroll
        for (int mt = 0; mt < 4; ++mt) {
            int r0 = mBase + mwarp * 64 + mt * 16 + g;
            int r1 = r0 + 8;
            if (r0 < M) {
                float2 v;
                v.x = eluf(acc[mt][nt2][0] + b0);
                v.y = eluf(acc[mt][nt2][1] + b1);
                *reinterpret_cast<float2*>(C + (size_t)r0 * NSKIP + col) = v;
            }
            if (r1 < M) {
                float2 v;
                v.x = eluf(acc[mt][nt2][2] + b0);
                v.y = eluf(acc[mt][nt2][3] + b1);
                *reinterpret_cast<float2*>(C + (size_t)r1 * NSKIP + col) = v;
            }
        }
    }
}

// Wrapper kernels: device-global pointers formed in DEVICE code.
__global__ __launch_bounds__(256) void skip_gemm_kernel(int M)
{
    mma_gemm_core<KSKIP>(g_G, g_WskipT, g_bskip, g_skip, M);
}
__global__ __launch_bounds__(256) void post1_gemm_kernel(
    const float* __restrict__ w_post1, const float* __restrict__ b_post1, int M)
{
    mma_gemm_core<NSKIP>(g_skip, w_post1, b_post1, g_y2, M);
}

// ------------------------------ post2 --------------------------------------
__global__ __launch_bounds__(256) void post2_kernel(
    const float* __restrict__ w2, const float* __restrict__ b2,
    float* __restrict__ out, int M)
{
    int gw = (blockIdx.x * 256 + threadIdx.x) >> 5;
    int lane = threadIdx.x & 31;
    if (gw >= M) return;
    const float* row = g_y2 + (size_t)gw * NSKIP;
    float acc = 0.f;
#pragma unroll
    for (int k = 0; k < 16; ++k)
        acc = fmaf(row[lane + 32 * k], w2[lane + 32 * k], acc);
#pragma unroll
    for (int s = 16; s > 0; s >>= 1)
        acc += __shfl_xor_sync(0xffffffffu, acc, s);
    if (lane == 0) out[gw] = acc + b2[0];
}

// ------------------------------ launch -------------------------------------
extern "C" void kernel_launch(void* const* d_in, const int* in_sizes, int n_in,
                              void* d_out, int out_size)
{
    const float* x       = (const float*)d_in[0];
    const float* w_in    = (const float*)d_in[1];
    const float* b_in    = (const float*)d_in[2];
    const float* w_sig   = (const float*)d_in[3];
    const float* b_sig   = (const float*)d_in[4];
    const float* w_tanh  = (const float*)d_in[5];
    const float* b_tanh  = (const float*)d_in[6];
    const float* w_skip  = (const float*)d_in[7];
    const float* b_skip  = (const float*)d_in[8];
    const float* w_res   = (const float*)d_in[9];
    const float* b_res   = (const float*)d_in[10];
    const float* w_post1 = (const float*)d_in[11];
    const float* b_post1 = (const float*)d_in[12];
    const float* w_post2 = (const float*)d_in[13];
    const float* b_post2 = (const float*)d_in[14];
    float* out = (float*)d_out;

    cudaFuncSetAttribute(layer_kernel,
                         cudaFuncAttributeMaxDynamicSharedMemorySize, LK_SMEM);
    cudaFuncSetAttribute(skip_gemm_kernel,
                         cudaFuncAttributeMaxDynamicSharedMemorySize, GSM_BYTES);
    cudaFuncSetAttribute(post1_gemm_kernel,
                         cudaFuncAttributeMaxDynamicSharedMemorySize, GSM_BYTES);

    in_conv_kernel<<<dim3(T_LEN / 8, BATCH), 256>>>(x, w_in, b_in);

    repack_weights_kernel<<<(NLAY * WPK + 255) / 256, 256>>>(
        w_sig, b_sig, w_tanh, b_tanh, w_res, b_res);
    repack_wskipT_kernel<<<(NSKIP * KSKIP) / 256, 256>>>(w_skip);
    bias_sum_kernel<<<2, 256>>>(b_skip);

    static const int dil10[10] = {1, 2, 4, 8, 16, 32, 64, 128, 256, 512};
    int L = T_LEN;
    for (int i = 0; i < NLAY; ++i) {
        int d = dil10[i % 10];
        int Lout = L - d;
        int goff = Lout - OUTLEN;
        int nb = (Lout + LTS - 1) / LTS;
        layer_kernel<<<dim3(nb, BATCH), 256, LK_SMEM>>>(i, d, Lout, goff, i & 1);
        L = Lout;
    }

    int M = MROWS;
    dim3 ggrid(NSKIP / 128, (M + 127) / 128);   // n fastest for A reuse in L2
    skip_gemm_kernel<<<ggrid, 256, GSM_BYTES>>>(M);
    post1_gemm_kernel<<<ggrid, 256, GSM_BYTES>>>(w_post1, b_post1, M);
    post2_kernel<<<(M + 7) / 8, 256>>>(w_post2, b_post2, out, M);
}